// round 16
// baseline (speedup 1.0000x reference)
#include <cuda_runtime.h>
#include <cuda_bf16.h>
#include <cstdint>
#include <stdint.h>
#include <math.h>

#define BATCH   32
#define NCAPS   1152
#define ILEN    32
#define OCAPS   64
#define OLEN    32
#define CLU     4                  // CTAs per cluster (one cluster per batch)
#define NPC     (NCAPS / CLU)      // 288 input caps per CTA
#define OPC     (OCAPS / CLU)      // 16 output caps per CTA
#define TPB     768
#define NWARP   24
#define NPW1    24                 // n per warp in phase 1a (12 n-groups x 2 halves)
#define NG2     3                  // n-groups in phase 2 (96 n each)
#define SLOTS   (CLU * NG2)        // 12 reduction slots

// SMEM layout (float offsets)
#define XS_OFF  0                            // xs  [288][32]      9216
#define PS_OFF  (XS_OFF + NPC * ILEN)        // ps  [288][64]     18432
#define TT_OFF  (PS_OFF + NPC * OCAPS)       // tT2 [16][64] f2    2048
#define SP_OFF  (TT_OFF + 16 * OCAPS * 2)    // sp  [12][16][32]   6144
#define SX_OFF  (SP_OFF + SLOTS * OPC * 32)  // sx  [4][32]         128
#define ZV_OFF  (SX_OFF + CLU * 32)          // Zinv [288]          288
#define WS_OFF  (ZV_OFF + NPC)               // Wsm [16][32][33]  16896
#define SM_FLOATS (WS_OFF + OPC * 32 * 33)
#define SM_BYTES  (SM_FLOATS * 4)            // ~212.6 KB

__device__ __forceinline__ unsigned int smem_u32(const void* p) {
    unsigned int a;
    asm("{ .reg .u64 t; cvta.to.shared.u64 t, %1; cvt.u32.u64 %0, t; }"
        : "=r"(a) : "l"(p));
    return a;
}
__device__ __forceinline__ unsigned int mapa_rank(unsigned int laddr,
                                                  unsigned int rank) {
    unsigned int r;
    asm("mapa.shared::cluster.u32 %0, %1, %2;" : "=r"(r) : "r"(laddr), "r"(rank));
    return r;
}
__device__ __forceinline__ void st_clu(unsigned int raddr, float v) {
    asm volatile("st.shared::cluster.f32 [%0], %1;" :: "r"(raddr), "f"(v) : "memory");
}
#define CLUSTER_SYNC() do { \
    asm volatile("barrier.cluster.arrive.aligned;" ::: "memory"); \
    asm volatile("barrier.cluster.wait.aligned;" ::: "memory"); \
} while (0)

// packed fp32x2 helpers (FFMA2 path — only reachable via PTX)
__device__ __forceinline__ void ffma2(unsigned long long& d,
                                      unsigned long long a,
                                      unsigned long long b) {
    asm("fma.rn.f32x2 %0, %1, %2, %0;" : "+l"(d) : "l"(a), "l"(b));
}
__device__ __forceinline__ float2 unpack2(unsigned long long v) {
    float2 r;
    asm("mov.b64 {%0, %1}, %2;" : "=f"(r.x), "=f"(r.y) : "l"(v));
    return r;
}
__device__ __forceinline__ unsigned long long splat2(float v) {
    unsigned long long r;
    asm("mov.b64 %0, {%1, %1};" : "=l"(r) : "f"(v));
    return r;
}

// p1b worker: softmax over one half-row (n, h) of ps; partner half on lane^1.
// Rotated scalar column index (k+lane)&31 -> bank-conflict-free (permutation).
__device__ __forceinline__ void softmax_halfrow(float* ps, float* ZV,
                                                int n, int h, int lane) {
    float* row = ps + n * OCAPS + h * 32;
    float d[32];
    #pragma unroll
    for (int k = 0; k < 32; k++) d[k] = row[(k + lane) & 31];
    float m[8];
    #pragma unroll
    for (int j = 0; j < 8; j++) m[j] = d[j];
    #pragma unroll
    for (int k = 8; k < 32; k++) m[k & 7] = fmaxf(m[k & 7], d[k]);
    float mx = fmaxf(fmaxf(fmaxf(m[0], m[1]), fmaxf(m[2], m[3])),
                     fmaxf(fmaxf(m[4], m[5]), fmaxf(m[6], m[7])));
    mx = fmaxf(mx, __shfl_xor_sync(0xffffffffu, mx, 1));   // combine halves
    #pragma unroll
    for (int k = 0; k < 32; k++) d[k] = __expf(d[k] - mx);
    float z[8];
    #pragma unroll
    for (int j = 0; j < 8; j++) z[j] = d[j];
    #pragma unroll
    for (int k = 8; k < 32; k++) z[k & 7] += d[k];
    float Z = ((z[0] + z[1]) + (z[2] + z[3])) + ((z[4] + z[5]) + (z[6] + z[7]));
    Z += __shfl_xor_sync(0xffffffffu, Z, 1);                // combine halves
    if (h == 0) ZV[n] = __fdividef(1.0f, Z);
    #pragma unroll
    for (int k = 0; k < 32; k++) row[(k + lane) & 31] = d[k];
}

// ---------------------------------------------------------------------------
// Persistent clustered kernel, 768 threads (24 warps), 1 CTA/SM, 85-reg cap.
// ---------------------------------------------------------------------------
__global__ void __cluster_dims__(CLU, 1, 1) __launch_bounds__(TPB, 1)
k_caps(const float* __restrict__ x, const float* __restrict__ w,
       float* __restrict__ out) {
    extern __shared__ float sm[];
    float* xs  = sm + XS_OFF;
    float* ps  = sm + PS_OFF;
    float* tT  = sm + TT_OFF;    // [j=i/2][o] float2 (packed i-pairs)
    float* sp  = sm + SP_OFF;
    float* sx  = sm + SX_OFF;
    float* ZV  = sm + ZV_OFF;
    float* Wsm = sm + WS_OFF;    // [oo][l][33]

    const int b    = blockIdx.y;
    const int rank = blockIdx.x;
    const int t    = threadIdx.x;
    const int lane = t & 31;
    const int wp   = t >> 5;                 // 0..23

    // ---- load x slice [288][32] ----
    {
        const float4* src = (const float4*)&x[((size_t)b * NCAPS + rank * NPC) * ILEN];
        float4* dst = (float4*)xs;
        #pragma unroll
        for (int k = 0; k < 3; k++) dst[t + k * TPB] = src[t + k * TPB];
    }
    // ---- load W slice (vectorized LDG) into SMEM [oo][l][33] ----
    {
        const float4* wsrc = (const float4*)&w[(size_t)(rank * OPC) * OLEN * ILEN];
        for (int idx = t; idx < OPC * OLEN * ILEN / 4; idx += TPB) {
            const float4 v = wsrc[idx];
            const int f   = idx * 4;
            const int oo  = f >> 10;
            const int rem = f & 1023;
            float* dst = &Wsm[oo * (32 * 33) + (rem >> 5) * 33 + (rem & 31)];
            dst[0] = v.x; dst[1] = v.y; dst[2] = v.z; dst[3] = v.w;
        }
    }
    __syncthreads();

    // ---- iter 0: colsum partial -> broadcast to all peers ----
    {
        float acc = 0.f;
        #pragma unroll
        for (int k = 0; k < NPC / NWARP; k++)     // 12 rows per warp
            acc += xs[(wp + k * NWARP) * ILEN + lane];
        float* red = ps;                           // reuse ps area
        red[wp * 32 + lane] = acc;
        __syncthreads();
        if (t < 32) {
            float s = 0.f;
            #pragma unroll
            for (int k = 0; k < NWARP; k++) s += red[k * 32 + t];
            const unsigned int la = smem_u32(&sx[rank * 32 + t]);
            #pragma unroll
            for (int p = 0; p < CLU; p++) st_clu(mapa_rank(la, p), s);
        }
    }
    CLUSTER_SYNC();

    float t_acc = 0.f;   // cumulative t[o][i=lane], valid in warps wp<16

    // ================= 3 iterations =================
    for (int iter = 0; iter < 3; iter++) {
        if (iter > 0) {
            // ---- phase 1a: raw logits; warp owns one o-half x 24 n ----
            {
                const int h  = wp / 12;           // o-half
                const int ng = wp % 12;           // n-group (24 n)
                const int o1 = lane + 32 * h;
                unsigned long long tp[16];
                #pragma unroll
                for (int j = 0; j < 16; j++)
                    tp[j] = *(const unsigned long long*)&tT[(j * OCAPS + o1) * 2];
                #pragma unroll
                for (int k = 0; k < NPW1; k += 6) {
                    const int na = ng * NPW1 + k;
                    unsigned long long acc[6] = {0, 0, 0, 0, 0, 0};
                    #pragma unroll
                    for (int j = 0; j < 6; j++) {
                        const ulonglong2* xr = (const ulonglong2*)&xs[(na + j) * ILEN];
                        #pragma unroll
                        for (int m = 0; m < 8; m++) {
                            const ulonglong2 v = xr[m];
                            ffma2(acc[j], tp[2*m], v.x);
                            ffma2(acc[j], tp[2*m+1], v.y);
                        }
                    }
                    #pragma unroll
                    for (int j = 0; j < 6; j++) {
                        const float2 u = unpack2(acc[j]);
                        ps[(na + j) * OCAPS + o1] = u.x + u.y;
                    }
                }
            }
            __syncthreads();

            // ---- phase 1b: two-pass softmax, half-row per thread ----
            if (t < 2 * NPC)   // 576 tasks over warps 0..17
                softmax_halfrow(ps, ZV, t >> 1, t & 1, lane);
            __syncthreads();

            // ---- phase 2: o-packed partial s; 3 n-groups x 8 warps x 8 o ----
            const int g  = wp / 8;               // n-group: [g*96, g*96+96)
            const int ow = (wp % 8) * 8;         // 8 o's
            unsigned long long ac0 = 0, ac1 = 0, ac2 = 0, ac3 = 0;
            const int nbeg = g * (NPC / NG2);
            #pragma unroll 8
            for (int n = nbeg; n < nbeg + NPC / NG2; n++) {
                const unsigned long long xx =
                    splat2(xs[n * ILEN + lane] * ZV[n]);   // fold 1/Z here
                const ulonglong2* pp = (const ulonglong2*)&ps[n * OCAPS + ow];
                const ulonglong2 p0 = pp[0];
                const ulonglong2 p1 = pp[1];
                ffma2(ac0, p0.x, xx); ffma2(ac1, p0.y, xx);
                ffma2(ac2, p1.x, xx); ffma2(ac3, p1.y, xx);
            }
            // deliver 8 o-rows to owner CTA's slot [rank*NG2+g]
            {
                const unsigned int owner = (unsigned int)(ow >> 4);
                const int ol   = ow & 15;            // 0 or 8
                const int slot = rank * NG2 + g;
                const unsigned int la =
                    smem_u32(&sp[(slot * OPC + ol) * 32 + lane]);
                const unsigned int ra = mapa_rank(la, owner);
                const float2 u0 = unpack2(ac0), u1 = unpack2(ac1);
                const float2 u2 = unpack2(ac2), u3 = unpack2(ac3);
                st_clu(ra +   0, u0.x); st_clu(ra + 128, u0.y);
                st_clu(ra + 256, u1.x); st_clu(ra + 384, u1.y);
                st_clu(ra + 512, u2.x); st_clu(ra + 640, u2.y);
                st_clu(ra + 768, u3.x); st_clu(ra + 896, u3.y);
            }
            CLUSTER_SYNC();
        }

        // ---- out/t step: warps 0..15 own one o each (W + bcasts in SMEM) ----
        if (wp < OPC) {
            const int o = rank * OPC + wp;
            float s_l;
            if (iter == 0) {
                s_l = (sx[lane] + sx[32 + lane] + sx[64 + lane] + sx[96 + lane])
                      * (1.0f / OCAPS);
            } else {
                s_l = 0.f;
                #pragma unroll
                for (int slot = 0; slot < SLOTS; slot++)
                    s_l += sp[(slot * OPC + wp) * 32 + lane];
            }

            const float* wtile = &Wsm[wp * (32 * 33)];
            float* ssm = ps + wp * 36;   // per-warp broadcast scratch (ps dead)

            // out[l=lane] = sum_i W[o][lane][i] * s[i]
            ssm[lane] = s_l;
            __syncwarp();
            float a0 = 0.f, a1 = 0.f, a2 = 0.f, a3 = 0.f;
            #pragma unroll
            for (int m = 0; m < 8; m++) {
                const float4 sv = *(const float4*)&ssm[m * 4];  // broadcast
                a0 += wtile[lane * 33 + m * 4 + 0] * sv.x;
                a1 += wtile[lane * 33 + m * 4 + 1] * sv.y;
                a2 += wtile[lane * 33 + m * 4 + 2] * sv.z;
                a3 += wtile[lane * 33 + m * 4 + 3] * sv.w;
            }
            float out_l = (a0 + a1) + (a2 + a3);

            float ss = out_l * out_l;
            #pragma unroll
            for (int off = 16; off; off >>= 1)
                ss += __shfl_xor_sync(0xffffffffu, ss, off);
            out_l *= __fdividef(sqrtf(ss), 1.0f + ss);

            if (iter == 2) {
                out[((size_t)b * OCAPS + o) * OLEN + lane] = out_l;
            } else {
                // t[i=lane] = sum_l W[o][l][lane] * out[l]
                __syncwarp();
                ssm[lane] = out_l;
                __syncwarp();
                float b0 = 0.f, b1 = 0.f, b2 = 0.f, b3 = 0.f;
                #pragma unroll
                for (int m = 0; m < 8; m++) {
                    const float4 ov = *(const float4*)&ssm[m * 4];  // broadcast
                    b0 += wtile[(m * 4 + 0) * 33 + lane] * ov.x;
                    b1 += wtile[(m * 4 + 1) * 33 + lane] * ov.y;
                    b2 += wtile[(m * 4 + 2) * 33 + lane] * ov.z;
                    b3 += wtile[(m * 4 + 3) * 33 + lane] * ov.w;
                }
                t_acc += (b0 + b1) + (b2 + b3);     // cumulative agreement
                // write packed-transposed: tT2[j = lane/2][o], element lane&1
                const unsigned int la =
                    smem_u32(&tT[((lane >> 1) * OCAPS + o) * 2 + (lane & 1)]);
                #pragma unroll
                for (int p = 0; p < CLU; p++) st_clu(mapa_rank(la, p), t_acc);
            }
        }
        if (iter < 2) CLUSTER_SYNC();
    }
}

// ---------------------------------------------------------------------------
extern "C" void kernel_launch(void* const* d_in, const int* in_sizes, int n_in,
                              void* d_out, int out_size) {
    const float* x = (const float*)d_in[0];   // [32,1152,32]
    const float* w = (const float*)d_in[1];   // [64,32,32]
    float* out = (float*)d_out;               // [32,64,32]

    cudaFuncSetAttribute(k_caps, cudaFuncAttributeMaxDynamicSharedMemorySize,
                         SM_BYTES);
    k_caps<<<dim3(CLU, BATCH), TPB, SM_BYTES>>>(x, w, out);
}

// round 17
// speedup vs baseline: 1.1723x; 1.1723x over previous
#include <cuda_runtime.h>
#include <cuda_bf16.h>
#include <cstdint>
#include <stdint.h>
#include <math.h>

#define BATCH   32
#define NCAPS   1152
#define ILEN    32
#define OCAPS   64
#define OLEN    32
#define CLU     4                  // CTAs per cluster (one cluster per batch)
#define NPC     (NCAPS / CLU)      // 288 input caps per CTA
#define OPC     (OCAPS / CLU)      // 16 output caps per CTA
#define TPB     512
#define NWARP   16
#define NPW     (NPC / NWARP)      // 18 n per warp in phase 1a
#define NG2     4                  // phase-2 n-groups (72 n each)
#define SLOTS   (CLU * NG2)        // 16 reduction slots

// SMEM layout (float offsets)
#define XS_OFF  0                            // xs  [288][32]      9216
#define PS_OFF  (XS_OFF + NPC * ILEN)        // ps  [288][64]     18432
#define TT_OFF  (PS_OFF + NPC * OCAPS)       // tT2 [16][64] f2    2048
#define SP_OFF  (TT_OFF + 16 * OCAPS * 2)    // sp  [16][16][32]   8192
#define SX_OFF  (SP_OFF + SLOTS * OPC * 32)  // sx  [4][32]         128
#define WS_OFF  (SX_OFF + CLU * 32)          // Wsm [16][32][33]  16896
#define SM_FLOATS (WS_OFF + OPC * 32 * 33)
#define SM_BYTES  (SM_FLOATS * 4)            // ~219.6 KB

__device__ __forceinline__ unsigned int smem_u32(const void* p) {
    unsigned int a;
    asm("{ .reg .u64 t; cvta.to.shared.u64 t, %1; cvt.u32.u64 %0, t; }"
        : "=r"(a) : "l"(p));
    return a;
}
__device__ __forceinline__ unsigned int mapa_rank(unsigned int laddr,
                                                  unsigned int rank) {
    unsigned int r;
    asm("mapa.shared::cluster.u32 %0, %1, %2;" : "=r"(r) : "r"(laddr), "r"(rank));
    return r;
}
__device__ __forceinline__ void st_clu(unsigned int raddr, float v) {
    asm volatile("st.shared::cluster.f32 [%0], %1;" :: "r"(raddr), "f"(v) : "memory");
}
#define CLUSTER_SYNC() do { \
    asm volatile("barrier.cluster.arrive.aligned;" ::: "memory"); \
    asm volatile("barrier.cluster.wait.aligned;" ::: "memory"); \
} while (0)

// packed fp32x2 helpers (FFMA2 path — only reachable via PTX)
__device__ __forceinline__ void ffma2(unsigned long long& d,
                                      unsigned long long a,
                                      unsigned long long b) {
    asm("fma.rn.f32x2 %0, %1, %2, %0;" : "+l"(d) : "l"(a), "l"(b));
}
__device__ __forceinline__ float2 unpack2(unsigned long long v) {
    float2 r;
    asm("mov.b64 {%0, %1}, %2;" : "=f"(r.x), "=f"(r.y) : "l"(v));
    return r;
}
__device__ __forceinline__ unsigned long long splat2(float v) {
    unsigned long long r;
    asm("mov.b64 %0, {%1, %1};" : "=l"(r) : "f"(v));
    return r;
}

// p1b: softmax over one half-row (n, h) of ps; partner half on lane^1.
// Rotated scalar column index (k+lane)&31 -> bank-conflict-free (permutation).
// Writes back NORMALIZED probs (1/Z folded here, not in phase 2).
__device__ __forceinline__ void softmax_halfrow(float* ps, int n, int h,
                                                int lane) {
    float* row = ps + n * OCAPS + h * 32;
    float d[32];
    #pragma unroll
    for (int k = 0; k < 32; k++) d[k] = row[(k + lane) & 31];
    float m[8];
    #pragma unroll
    for (int j = 0; j < 8; j++) m[j] = d[j];
    #pragma unroll
    for (int k = 8; k < 32; k++) m[k & 7] = fmaxf(m[k & 7], d[k]);
    float mx = fmaxf(fmaxf(fmaxf(m[0], m[1]), fmaxf(m[2], m[3])),
                     fmaxf(fmaxf(m[4], m[5]), fmaxf(m[6], m[7])));
    mx = fmaxf(mx, __shfl_xor_sync(0xffffffffu, mx, 1));   // combine halves
    #pragma unroll
    for (int k = 0; k < 32; k++) d[k] = __expf(d[k] - mx);
    float z[8];
    #pragma unroll
    for (int j = 0; j < 8; j++) z[j] = d[j];
    #pragma unroll
    for (int k = 8; k < 32; k++) z[k & 7] += d[k];
    float Z = ((z[0] + z[1]) + (z[2] + z[3])) + ((z[4] + z[5]) + (z[6] + z[7]));
    Z += __shfl_xor_sync(0xffffffffu, Z, 1);                // combine halves
    const float inv = __fdividef(1.0f, Z);
    #pragma unroll
    for (int k = 0; k < 32; k++) row[(k + lane) & 31] = d[k] * inv;
}

// ---------------------------------------------------------------------------
// Persistent clustered kernel, 512 threads (16 warps), 1 CTA/SM.
// ---------------------------------------------------------------------------
__global__ void __cluster_dims__(CLU, 1, 1) __launch_bounds__(TPB, 1)
k_caps(const float* __restrict__ x, const float* __restrict__ w,
       float* __restrict__ out) {
    extern __shared__ float sm[];
    float* xs  = sm + XS_OFF;
    float* ps  = sm + PS_OFF;
    float* tT  = sm + TT_OFF;    // [j=i/2][o] float2 (packed i-pairs)
    float* sp  = sm + SP_OFF;
    float* sx  = sm + SX_OFF;
    float* Wsm = sm + WS_OFF;    // [oo][l][33]

    const int b    = blockIdx.y;
    const int rank = blockIdx.x;
    const int t    = threadIdx.x;
    const int lane = t & 31;
    const int wp   = t >> 5;
    const int o    = rank * OPC + wp;      // this warp's owned output capsule

    // ---- load x slice [288][32] ----
    {
        const float4* src = (const float4*)&x[((size_t)b * NCAPS + rank * NPC) * ILEN];
        float4* dst = (float4*)xs;
        #pragma unroll
        for (int idx = t; idx < NPC * ILEN / 4; idx += TPB) dst[idx] = src[idx];
    }
    // ---- load W slice (vectorized LDG) into SMEM [oo][l][33] ----
    {
        const float4* wsrc = (const float4*)&w[(size_t)(rank * OPC) * OLEN * ILEN];
        for (int idx = t; idx < OPC * OLEN * ILEN / 4; idx += TPB) {
            const float4 v = wsrc[idx];
            const int f   = idx * 4;
            const int oo  = f >> 10;
            const int rem = f & 1023;
            float* dst = &Wsm[oo * (32 * 33) + (rem >> 5) * 33 + (rem & 31)];
            dst[0] = v.x; dst[1] = v.y; dst[2] = v.z; dst[3] = v.w;
        }
    }
    __syncthreads();

    // ---- iter 0: colsum partial -> broadcast to all peers ----
    {
        float acc = 0.f;
        #pragma unroll
        for (int k = 0; k < NPW; k++)
            acc += xs[(wp + k * NWARP) * ILEN + lane];
        float* red = ps;                   // reuse ps area
        red[wp * 32 + lane] = acc;
        __syncthreads();
        if (t < 32) {
            float s = 0.f;
            #pragma unroll
            for (int k = 0; k < NWARP; k++) s += red[k * 32 + t];
            const unsigned int la = smem_u32(&sx[rank * 32 + t]);
            #pragma unroll
            for (int p = 0; p < CLU; p++) st_clu(mapa_rank(la, p), s);
        }
    }
    CLUSTER_SYNC();

    float t_acc = 0.f;   // cumulative t[o][i=lane] across iterations

    // ================= 3 iterations =================
    for (int iter = 0; iter < 3; iter++) {
        if (iter > 0) {
            // ---- phase 1a: raw logits only (no reductions), 6-way n ILP ----
            {
                unsigned long long tp0[16], tp1[16];
                #pragma unroll
                for (int j = 0; j < 16; j++) {
                    tp0[j] = *(const unsigned long long*)&tT[(j * OCAPS + lane) * 2];
                    tp1[j] = *(const unsigned long long*)&tT[(j * OCAPS + lane + 32) * 2];
                }
                #pragma unroll
                for (int k = 0; k < NPW; k += 6) {
                    const int na = wp * NPW + k;
                    unsigned long long acc[6][2];
                    #pragma unroll
                    for (int j = 0; j < 6; j++) { acc[j][0] = 0; acc[j][1] = 0; }
                    #pragma unroll
                    for (int j = 0; j < 6; j++) {
                        const ulonglong2* xr = (const ulonglong2*)&xs[(na + j) * ILEN];
                        #pragma unroll
                        for (int m = 0; m < 8; m++) {
                            const ulonglong2 v = xr[m];
                            ffma2(acc[j][0], tp0[2*m], v.x);
                            ffma2(acc[j][0], tp0[2*m+1], v.y);
                            ffma2(acc[j][1], tp1[2*m], v.x);
                            ffma2(acc[j][1], tp1[2*m+1], v.y);
                        }
                    }
                    #pragma unroll
                    for (int j = 0; j < 6; j++) {
                        const float2 u0 = unpack2(acc[j][0]);
                        const float2 u1 = unpack2(acc[j][1]);
                        ps[(na + j) * OCAPS + lane]      = u0.x + u0.y;
                        ps[(na + j) * OCAPS + lane + 32] = u1.x + u1.y;
                    }
                }
            }
            __syncthreads();

            // ---- phase 1b: two-pass softmax (normalized writeback) ----
            softmax_halfrow(ps, t >> 1, t & 1, lane);            // n 0..255
            if (t < 64)
                softmax_halfrow(ps, 256 + (t >> 1), t & 1, lane); // n 256..287
            __syncthreads();

            // ---- phase 2: 4 n-groups x 4 o-groups; warp owns 16 o ----
            const int g_n = wp >> 2;             // n-group: [g_n*72, +72)
            const int g_o = wp & 3;              // o-group (= owner CTA)
            const int ow  = g_o * 16;
            unsigned long long ac[8];
            #pragma unroll
            for (int j = 0; j < 8; j++) ac[j] = 0;
            const int nbeg = g_n * (NPC / NG2);
            #pragma unroll 4
            for (int n = nbeg; n < nbeg + NPC / NG2; n++) {
                const unsigned long long xx = splat2(xs[n * ILEN + lane]);
                const ulonglong2* pp = (const ulonglong2*)&ps[n * OCAPS + ow];
                const ulonglong2 p0 = pp[0];
                const ulonglong2 p1 = pp[1];
                const ulonglong2 p2 = pp[2];
                const ulonglong2 p3 = pp[3];
                ffma2(ac[0], p0.x, xx); ffma2(ac[1], p0.y, xx);
                ffma2(ac[2], p1.x, xx); ffma2(ac[3], p1.y, xx);
                ffma2(ac[4], p2.x, xx); ffma2(ac[5], p2.y, xx);
                ffma2(ac[6], p3.x, xx); ffma2(ac[7], p3.y, xx);
            }
            // deliver 16 o-rows to owner CTA g_o, slot [rank*NG2+g_n]
            {
                const int slot = rank * NG2 + g_n;
                const unsigned int la =
                    smem_u32(&sp[(slot * OPC) * 32 + lane]);
                const unsigned int ra = mapa_rank(la, (unsigned int)g_o);
                #pragma unroll
                for (int j = 0; j < 8; j++) {
                    const float2 u = unpack2(ac[j]);
                    st_clu(ra + (2 * j)     * 128, u.x);
                    st_clu(ra + (2 * j + 1) * 128, u.y);
                }
            }
            CLUSTER_SYNC();
        }

        // ---- out/t step: warp handles its owned o (W + bcasts in SMEM) ----
        float s_l;
        if (iter == 0) {
            s_l = (sx[lane] + sx[32 + lane] + sx[64 + lane] + sx[96 + lane])
                  * (1.0f / OCAPS);
        } else {
            s_l = 0.f;
            #pragma unroll
            for (int slot = 0; slot < SLOTS; slot++)
                s_l += sp[(slot * OPC + wp) * 32 + lane];
        }

        const float* wtile = &Wsm[wp * (32 * 33)];
        float* ssm = ps + wp * 36;     // per-warp broadcast scratch (ps dead here)

        // out[l=lane] = sum_i W[o][lane][i] * s[i]  (smem broadcast, 4-way split)
        ssm[lane] = s_l;
        __syncwarp();
        float a0 = 0.f, a1 = 0.f, a2 = 0.f, a3 = 0.f;
        #pragma unroll
        for (int m = 0; m < 8; m++) {
            const float4 sv = *(const float4*)&ssm[m * 4];     // broadcast LDS.128
            a0 += wtile[lane * 33 + m * 4 + 0] * sv.x;
            a1 += wtile[lane * 33 + m * 4 + 1] * sv.y;
            a2 += wtile[lane * 33 + m * 4 + 2] * sv.z;
            a3 += wtile[lane * 33 + m * 4 + 3] * sv.w;
        }
        float out_l = (a0 + a1) + (a2 + a3);

        float ss = out_l * out_l;
        #pragma unroll
        for (int off = 16; off; off >>= 1)
            ss += __shfl_xor_sync(0xffffffffu, ss, off);
        out_l *= __fdividef(sqrtf(ss), 1.0f + ss);

        if (iter == 2) {
            out[((size_t)b * OCAPS + o) * OLEN + lane] = out_l;
        } else {
            // t[i=lane] = sum_l W[o][l][lane] * out[l]  (smem broadcast, split)
            __syncwarp();
            ssm[lane] = out_l;
            __syncwarp();
            float b0 = 0.f, b1 = 0.f, b2 = 0.f, b3 = 0.f;
            #pragma unroll
            for (int m = 0; m < 8; m++) {
                const float4 ov = *(const float4*)&ssm[m * 4]; // broadcast LDS.128
                b0 += wtile[(m * 4 + 0) * 33 + lane] * ov.x;
                b1 += wtile[(m * 4 + 1) * 33 + lane] * ov.y;
                b2 += wtile[(m * 4 + 2) * 33 + lane] * ov.z;
                b3 += wtile[(m * 4 + 3) * 33 + lane] * ov.w;
            }
            t_acc += (b0 + b1) + (b2 + b3);     // cumulative agreement
            // write packed-transposed: tT2[j = lane/2][o], element lane&1
            const unsigned int la =
                smem_u32(&tT[((lane >> 1) * OCAPS + o) * 2 + (lane & 1)]);
            #pragma unroll
            for (int p = 0; p < CLU; p++) st_clu(mapa_rank(la, p), t_acc);
            CLUSTER_SYNC();
        }
    }
}

// ---------------------------------------------------------------------------
extern "C" void kernel_launch(void* const* d_in, const int* in_sizes, int n_in,
                              void* d_out, int out_size) {
    const float* x = (const float*)d_in[0];   // [32,1152,32]
    const float* w = (const float*)d_in[1];   // [64,32,32]
    float* out = (float*)d_out;               // [32,64,32]

    cudaFuncSetAttribute(k_caps, cudaFuncAttributeMaxDynamicSharedMemorySize,
                         SM_BYTES);
    k_caps<<<dim3(CLU, BATCH), TPB, SM_BYTES>>>(x, w, out);
}